// round 7
// baseline (speedup 1.0000x reference)
#include <cuda_runtime.h>
#include <cstddef>

#define TT 1024
#define BB 8
#define VV 32000
#define EE 32
#define HH 8
#define NROWS (TT*BB)      // 8192
#define VBLK  25           // grid.x of pass kernels
#define VITER 10           // outer iters; per iter a warp covers 16 n8-tiles = 128 v

// ---------------- scratch (device globals; no allocation) ----------------
__device__ float  g_xp[2*TT*BB*HH];      // [dir][t][b][h]  input projections (+both biases)
__device__ float  g_totalH[TT*16*BB];    // [t][d][b]  d<8: forward h1, d>=8: backward h2
__device__ float  g_partial[VBLK*NROWS]; // per v-block partial sum-of-exp (deterministic)
__device__ float  g_rowstat[NROWS];      // log(sum exp) per row
__device__ float2 g_W2[16*VV];           // tiled tf32 (hi,lo) pairs of output weights, 4 MB

// tf32 round (rna)
__device__ __forceinline__ unsigned tf32_of(float x) {
    unsigned r;
    asm("cvt.rna.tf32.f32 %0, %1;" : "=r"(r) : "f"(x));
    return r;
}

// m16n8k8 tf32 mma, D += A*B (C aliased to D)
__device__ __forceinline__ void mma_tf32(float& d0, float& d1, float& d2, float& d3,
                                         unsigned a0, unsigned a1, unsigned a2, unsigned a3,
                                         unsigned b0, unsigned b1) {
    asm("mma.sync.aligned.m16n8k8.row.col.f32.tf32.tf32.f32 "
        "{%0,%1,%2,%3}, {%4,%5,%6,%7}, {%8,%9}, {%0,%1,%2,%3};"
        : "+f"(d0), "+f"(d1), "+f"(d2), "+f"(d3)
        : "r"(a0), "r"(a1), "r"(a2), "r"(a3), "r"(b0), "r"(b1));
}

// ---------------- kernel 0: W -> tiled tf32 hi/lo pairs ----------------
// Layout: for v-tile vt (8 v), all 16 k rows contiguous: g_W2[(vt*16 + k)*8 + (v&7)]
__global__ void k_prep(const float* __restrict__ Wo) {
    int v = blockIdx.x * 256 + threadIdx.x;   // grid.x = 125
    int k = blockIdx.y;                        // 16
    float x = __ldg(Wo + (size_t)k * VV + v);
    unsigned hb = tf32_of(x);
    float hf = __uint_as_float(hb);
    unsigned lb = tf32_of(x - hf);
    g_W2[((v >> 3) * 16 + k) * 8 + (v & 7)] = make_float2(hf, __uint_as_float(lb));
}

// ---------------- kernel 1: embedding gather + x-projections ----------------
__global__ void k_embed(const int* __restrict__ x, const float* __restrict__ emb,
                        const float* __restrict__ Wx1, const float* __restrict__ bx1,
                        const float* __restrict__ bh1,
                        const float* __restrict__ Wx2, const float* __restrict__ bx2,
                        const float* __restrict__ bh2) {
    int tid = blockIdx.x * blockDim.x + threadIdx.x;   // (t,b) flat
    if (tid >= NROWS) return;
    int idx = x[tid];
    const float4* em = (const float4*)(emb + (size_t)idx * EE);
    float e[EE];
    #pragma unroll
    for (int q = 0; q < 8; q++) {
        float4 v = __ldg(em + q);
        e[4*q] = v.x; e[4*q+1] = v.y; e[4*q+2] = v.z; e[4*q+3] = v.w;
    }
    #pragma unroll
    for (int j = 0; j < HH; j++) {
        float s1 = bx1[j] + bh1[j];
        float s2 = bx2[j] + bh2[j];
        #pragma unroll
        for (int k = 0; k < EE; k++) {
            s1 = fmaf(e[k], __ldg(Wx1 + k*HH + j), s1);
            s2 = fmaf(e[k], __ldg(Wx2 + k*HH + j), s2);
        }
        g_xp[tid*HH + j] = s1;
        g_xp[TT*BB*HH + tid*HH + j] = s2;
    }
}

// ---------------- kernel 2: the two sequential RNNs ----------------
// 4 blocks x 32 threads. lane = chainLocal*8 + j; 4 chains per warp.
// h exchanged via shfl; xp loads prefetched 4 steps ahead.
// Emits h BEFORE the update (matches the reference scan).
__global__ void k_rnn(const float* __restrict__ Wh1, const float* __restrict__ Wh2) {
    int lane = threadIdx.x;
    int j = lane & 7;
    int c = blockIdx.x * 4 + (lane >> 3);   // chain id 0..15
    int dir = c >> 3, b = c & 7;
    int grp = lane & ~7;                    // base lane of this chain's group
    const float* Wh = dir ? Wh2 : Wh1;
    float w[HH];
    #pragma unroll
    for (int k = 0; k < HH; k++) w[k] = __ldg(Wh + k*HH + j);

    const float* xp = g_xp + dir * (TT*BB*HH);
    float h = 0.f;

    // depth-4 prefetch ring
    float pf[4];
    #pragma unroll
    for (int p = 0; p < 4; p++) {
        int t = dir ? (TT - 1 - p) : p;
        pf[p] = __ldg(xp + (t*BB + b) * HH + j);
    }

    #pragma unroll 4
    for (int s = 0; s < TT; s++) {
        int slot = s & 3;
        float xv = pf[slot];
        if (s + 4 < TT) {
            int t4 = dir ? (TT - 1 - (s + 4)) : (s + 4);
            pf[slot] = __ldg(xp + (t4*BB + b) * HH + j);
        }
        int t = dir ? (TT - 1 - s) : s;
        // emit pre-update hidden state
        g_totalH[(t*16 + dir*8 + j) * BB + b] = h;
        // z_j = xv + sum_k h_k * Wh[k][j]   (tree form)
        float h0 = __shfl_sync(0xffffffffu, h, grp + 0);
        float h1 = __shfl_sync(0xffffffffu, h, grp + 1);
        float h2 = __shfl_sync(0xffffffffu, h, grp + 2);
        float h3 = __shfl_sync(0xffffffffu, h, grp + 3);
        float h4 = __shfl_sync(0xffffffffu, h, grp + 4);
        float h5 = __shfl_sync(0xffffffffu, h, grp + 5);
        float h6 = __shfl_sync(0xffffffffu, h, grp + 6);
        float h7 = __shfl_sync(0xffffffffu, h, grp + 7);
        float t0 = fmaf(h1, w[1], h0 * w[0]);
        float t1 = fmaf(h3, w[3], h2 * w[2]);
        float t2 = fmaf(h5, w[5], h4 * w[4]);
        float t3 = fmaf(h7, w[7], h6 * w[6]);
        float z  = xv + ((t0 + t1) + (t2 + t3));
        h = __fdividef(1.f, 1.f + __expf(-z));
    }
}

// ---------------- pass kernels: tf32 3x mma GEMM + softmax stats / output ----------------
// Block = 256 thr (8 warps). Warp w owns 32 rows (two m16 A tiles) so each
// 1 KB B tile load is reused by 2x the outputs. rowBase = by*256 + w*32.
// Per outer iter each warp covers 128 v (16 n8-tiles); VITER iters per block.
template <bool PASS1>
__global__ __launch_bounds__(256) void k_pass(float* __restrict__ out) {
    int lane = threadIdx.x & 31, w = threadIdx.x >> 5;
    int g = lane >> 2, q = lane & 3;
    int rowBase = blockIdx.y * 256 + w * 32;

    // Two A tiles (hi/lo). frag jj: row g + (jj&1)*8, col q + (jj>>1)*4
    unsigned ah[2][2][4], al[2][2][4];   // [mtile][kt][frag]
    #pragma unroll
    for (int m = 0; m < 2; m++) {
        #pragma unroll
        for (int kt = 0; kt < 2; kt++) {
            #pragma unroll
            for (int jj = 0; jj < 4; jj++) {
                int r = g + (jj & 1) * 8;
                int k = kt * 8 + q + ((jj >> 1) ? 4 : 0);
                int grow = rowBase + m * 16 + r, t = grow >> 3, b = grow & 7;
                float v = g_totalH[(t*16 + k) * BB + b];
                unsigned hb = tf32_of(v);
                ah[m][kt][jj] = hb;
                al[m][kt][jj] = tf32_of(v - __uint_as_float(hb));
            }
        }
    }

    float st[4] = {0.f, 0.f, 0.f, 0.f};
    if (!PASS1) {
        st[0] = g_rowstat[rowBase + g];
        st[1] = g_rowstat[rowBase + g + 8];
        st[2] = g_rowstat[rowBase + g + 16];
        st[3] = g_rowstat[rowBase + g + 24];
    }

    float sum[4] = {0.f, 0.f, 0.f, 0.f};
    int vt0 = blockIdx.x * (VITER * 16);     // first v-tile of this block

    const float2* Bt = g_W2 + (size_t)vt0 * 128 + q * 8 + g;  // per-thread base
    float* op0;
    float* op1;
    float* op2;
    float* op3;
    if (!PASS1) {
        size_t vc = (size_t)vt0 * 8 + q * 2;
        op0 = out + (size_t)(rowBase + g     ) * VV + vc;
        op1 = out + (size_t)(rowBase + g +  8) * VV + vc;
        op2 = out + (size_t)(rowBase + g + 16) * VV + vc;
        op3 = out + (size_t)(rowBase + g + 24) * VV + vc;
    }

    for (int it = 0; it < VITER; it++) {
        #pragma unroll
        for (int nt = 0; nt < 16; nt++) {
            // B fragments for this n8-tile (one load, two A tiles consume it)
            float2 B00 = __ldg(Bt);          // kt=0, col q
            float2 B01 = __ldg(Bt + 32);     // kt=0, col q+4
            float2 B10 = __ldg(Bt + 64);     // kt=1, col q
            float2 B11 = __ldg(Bt + 96);     // kt=1, col q+4
            Bt += 128;
            unsigned b0h[2] = {__float_as_uint(B00.x), __float_as_uint(B10.x)};
            unsigned b0l[2] = {__float_as_uint(B00.y), __float_as_uint(B10.y)};
            unsigned b1h[2] = {__float_as_uint(B01.x), __float_as_uint(B11.x)};
            unsigned b1l[2] = {__float_as_uint(B01.y), __float_as_uint(B11.y)};

            float d[2][4];
            #pragma unroll
            for (int m = 0; m < 2; m++) {
                d[m][0] = d[m][1] = d[m][2] = d[m][3] = 0.f;
                #pragma unroll
                for (int kt = 0; kt < 2; kt++) {
                    mma_tf32(d[m][0],d[m][1],d[m][2],d[m][3],
                             ah[m][kt][0],ah[m][kt][1],ah[m][kt][2],ah[m][kt][3],
                             b0h[kt], b1h[kt]);
                    mma_tf32(d[m][0],d[m][1],d[m][2],d[m][3],
                             ah[m][kt][0],ah[m][kt][1],ah[m][kt][2],ah[m][kt][3],
                             b0l[kt], b1l[kt]);
                    mma_tf32(d[m][0],d[m][1],d[m][2],d[m][3],
                             al[m][kt][0],al[m][kt][1],al[m][kt][2],al[m][kt][3],
                             b0h[kt], b1h[kt]);
                }
            }

            if (PASS1) {
                sum[0] += __expf(d[0][0]) + __expf(d[0][1]);
                sum[1] += __expf(d[0][2]) + __expf(d[0][3]);
                sum[2] += __expf(d[1][0]) + __expf(d[1][1]);
                sum[3] += __expf(d[1][2]) + __expf(d[1][3]);
            } else {
                *(float2*)op0 = make_float2(d[0][0]-st[0], d[0][1]-st[0]);
                *(float2*)op1 = make_float2(d[0][2]-st[1], d[0][3]-st[1]);
                *(float2*)op2 = make_float2(d[1][0]-st[2], d[1][1]-st[2]);
                *(float2*)op3 = make_float2(d[1][2]-st[3], d[1][3]-st[3]);
                op0 += 8; op1 += 8; op2 += 8; op3 += 8;
            }
        }
    }

    if (PASS1) {
        // reduce across the 4 q-lanes sharing each row-group g
        #pragma unroll
        for (int i = 0; i < 4; i++) {
            sum[i] += __shfl_xor_sync(0xffffffffu, sum[i], 1);
            sum[i] += __shfl_xor_sync(0xffffffffu, sum[i], 2);
        }
        if (q == 0) {
            float* p = g_partial + (size_t)blockIdx.x * NROWS + rowBase;
            p[g     ] = sum[0];
            p[g +  8] = sum[1];
            p[g + 16] = sum[2];
            p[g + 24] = sum[3];
        }
    }
}

// ---------------- kernel: reduce partials -> log-sum-exp per row ----------------
__global__ void k_stat() {
    int r = blockIdx.x * blockDim.x + threadIdx.x;
    if (r >= NROWS) return;
    float s = 0.f;
    #pragma unroll
    for (int i = 0; i < VBLK; i++) s += g_partial[i * NROWS + r];
    g_rowstat[r] = logf(s);
}

// ---------------- launch ----------------
extern "C" void kernel_launch(void* const* d_in, const int* in_sizes, int n_in,
                              void* d_out, int out_size) {
    const int*   x   = (const int*)  d_in[0];
    const float* emb = (const float*)d_in[1];
    const float* Wx1 = (const float*)d_in[2];
    const float* bx1 = (const float*)d_in[3];
    const float* Wh1 = (const float*)d_in[4];
    const float* bh1 = (const float*)d_in[5];
    const float* Wx2 = (const float*)d_in[6];
    const float* bx2 = (const float*)d_in[7];
    const float* Wh2 = (const float*)d_in[8];
    const float* bh2 = (const float*)d_in[9];
    const float* Wo  = (const float*)d_in[10];
    float* out = (float*)d_out;

    dim3 gprep(125, 16);
    k_prep<<<gprep, 256>>>(Wo);
    k_embed<<<(NROWS + 255)/256, 256>>>(x, emb, Wx1, bx1, bh1, Wx2, bx2, bh2);
    k_rnn<<<4, 32>>>(Wh1, Wh2);
    dim3 grd(VBLK, NROWS/256), blk(256);
    k_pass<true ><<<grd, blk>>>(nullptr);
    k_stat<<<(NROWS + 255)/256, 256>>>();
    k_pass<false><<<grd, blk>>>(out);
}

// round 8
// speedup vs baseline: 1.1656x; 1.1656x over previous
#include <cuda_runtime.h>
#include <cstddef>

#define TT 1024
#define BB 8
#define VV 32000
#define EE 32
#define HH 8
#define NROWS (TT*BB)      // 8192
#define VBLK  25           // grid.x of pass kernels
#define VITER 10           // outer iters; per iter a warp covers 16 n8-tiles = 128 v

// ---------------- scratch (device globals; no allocation) ----------------
__device__ float  g_xp[2*TT*BB*HH];      // [dir][t][b][h]  input projections (+both biases)
__device__ float  g_totalH[TT*16*BB];    // [t][d][b]  d<8: forward h1, d>=8: backward h2
__device__ float  g_partial[VBLK*NROWS]; // per v-block partial sum-of-exp (deterministic)
__device__ float  g_rowstat[NROWS];      // log(sum exp) per row
__device__ float  g_Wt[16*VV];           // tiled tf32 output weights, 2 MB
// layout: tile vt (8 v), pos = vt*128 + kt*64 + n*8 + (k&3)*2 + ((k&7)>>2)
// so thread (g=n, q) loads float2 {k=kt*8+q, k=kt*8+q+4} at vt*128 + kt*64 + g*8 + q*2

// tf32 round (rna)
__device__ __forceinline__ unsigned tf32_of(float x) {
    unsigned r;
    asm("cvt.rna.tf32.f32 %0, %1;" : "=r"(r) : "f"(x));
    return r;
}

// m16n8k8 tf32 mma, D += A*B (C aliased to D)
__device__ __forceinline__ void mma_tf32(float& d0, float& d1, float& d2, float& d3,
                                         unsigned a0, unsigned a1, unsigned a2, unsigned a3,
                                         unsigned b0, unsigned b1) {
    asm("mma.sync.aligned.m16n8k8.row.col.f32.tf32.tf32.f32 "
        "{%0,%1,%2,%3}, {%4,%5,%6,%7}, {%8,%9}, {%0,%1,%2,%3};"
        : "+f"(d0), "+f"(d1), "+f"(d2), "+f"(d3)
        : "r"(a0), "r"(a1), "r"(a2), "r"(a3), "r"(b0), "r"(b1));
}

// ---------------- kernel 0: W -> tiled single-tf32 ----------------
__global__ void k_prep(const float* __restrict__ Wo) {
    int v = blockIdx.x * 256 + threadIdx.x;   // grid.x = 125
    int k = blockIdx.y;                        // 16
    float x = __ldg(Wo + (size_t)k * VV + v);
    int pos = (v >> 3) * 128 + (k >> 3) * 64 + (v & 7) * 8 + (k & 3) * 2 + ((k & 7) >> 2);
    g_Wt[pos] = __uint_as_float(tf32_of(x));
}

// ---------------- kernel 1: embedding gather + x-projections ----------------
__global__ void k_embed(const int* __restrict__ x, const float* __restrict__ emb,
                        const float* __restrict__ Wx1, const float* __restrict__ bx1,
                        const float* __restrict__ bh1,
                        const float* __restrict__ Wx2, const float* __restrict__ bx2,
                        const float* __restrict__ bh2) {
    int tid = blockIdx.x * blockDim.x + threadIdx.x;   // (t,b) flat
    if (tid >= NROWS) return;
    int idx = x[tid];
    const float4* em = (const float4*)(emb + (size_t)idx * EE);
    float e[EE];
    #pragma unroll
    for (int q = 0; q < 8; q++) {
        float4 v = __ldg(em + q);
        e[4*q] = v.x; e[4*q+1] = v.y; e[4*q+2] = v.z; e[4*q+3] = v.w;
    }
    #pragma unroll
    for (int j = 0; j < HH; j++) {
        float s1 = bx1[j] + bh1[j];
        float s2 = bx2[j] + bh2[j];
        #pragma unroll
        for (int k = 0; k < EE; k++) {
            s1 = fmaf(e[k], __ldg(Wx1 + k*HH + j), s1);
            s2 = fmaf(e[k], __ldg(Wx2 + k*HH + j), s2);
        }
        g_xp[tid*HH + j] = s1;
        g_xp[TT*BB*HH + tid*HH + j] = s2;
    }
}

// ---------------- kernel 2: the two sequential RNNs ----------------
// 4 blocks x 32 threads. lane = chainLocal*8 + j; 4 chains per warp.
// h exchanged via shfl; xp loads prefetched 4 steps ahead.
// Emits h BEFORE the update (matches the reference scan).
__global__ void k_rnn(const float* __restrict__ Wh1, const float* __restrict__ Wh2) {
    int lane = threadIdx.x;
    int j = lane & 7;
    int c = blockIdx.x * 4 + (lane >> 3);   // chain id 0..15
    int dir = c >> 3, b = c & 7;
    int grp = lane & ~7;                    // base lane of this chain's group
    const float* Wh = dir ? Wh2 : Wh1;
    float w[HH];
    #pragma unroll
    for (int k = 0; k < HH; k++) w[k] = __ldg(Wh + k*HH + j);

    const float* xp = g_xp + dir * (TT*BB*HH);
    float h = 0.f;

    // depth-4 prefetch ring
    float pf[4];
    #pragma unroll
    for (int p = 0; p < 4; p++) {
        int t = dir ? (TT - 1 - p) : p;
        pf[p] = __ldg(xp + (t*BB + b) * HH + j);
    }

    #pragma unroll 4
    for (int s = 0; s < TT; s++) {
        int slot = s & 3;
        float xv = pf[slot];
        if (s + 4 < TT) {
            int t4 = dir ? (TT - 1 - (s + 4)) : (s + 4);
            pf[slot] = __ldg(xp + (t4*BB + b) * HH + j);
        }
        int t = dir ? (TT - 1 - s) : s;
        // emit pre-update hidden state
        g_totalH[(t*16 + dir*8 + j) * BB + b] = h;
        // z_j = xv + sum_k h_k * Wh[k][j]   (tree form)
        float h0 = __shfl_sync(0xffffffffu, h, grp + 0);
        float h1 = __shfl_sync(0xffffffffu, h, grp + 1);
        float h2 = __shfl_sync(0xffffffffu, h, grp + 2);
        float h3 = __shfl_sync(0xffffffffu, h, grp + 3);
        float h4 = __shfl_sync(0xffffffffu, h, grp + 4);
        float h5 = __shfl_sync(0xffffffffu, h, grp + 5);
        float h6 = __shfl_sync(0xffffffffu, h, grp + 6);
        float h7 = __shfl_sync(0xffffffffu, h, grp + 7);
        float t0 = fmaf(h1, w[1], h0 * w[0]);
        float t1 = fmaf(h3, w[3], h2 * w[2]);
        float t2 = fmaf(h5, w[5], h4 * w[4]);
        float t3 = fmaf(h7, w[7], h6 * w[6]);
        float z  = xv + ((t0 + t1) + (t2 + t3));
        h = __fdividef(1.f, 1.f + __expf(-z));
    }
}

// ---------------- pass kernels: tf32 mma GEMM + softmax stats / output ----------------
// R4 geometry (best measured): warp owns 16 rows, block 256 = 128 rows,
// grid (VBLK, 64). A is split hi/lo (exact), B is single tf32 (rounded once):
// 4 MMAs + 2 LDG.64 per warp-tile.
template <bool PASS1>
__global__ __launch_bounds__(256) void k_pass(float* __restrict__ out) {
    int lane = threadIdx.x & 31, w = threadIdx.x >> 5;
    int g = lane >> 2, q = lane & 3;
    int rowBase = blockIdx.y * 128 + w * 16;

    // A fragments (hi/lo), loaded once. jj: row g+(jj&1)*8, col q+(jj>>1)*4
    unsigned ah[2][4], al[2][4];
    #pragma unroll
    for (int kt = 0; kt < 2; kt++) {
        #pragma unroll
        for (int jj = 0; jj < 4; jj++) {
            int r = g + (jj & 1) * 8;
            int k = kt * 8 + q + ((jj >> 1) ? 4 : 0);
            int grow = rowBase + r, t = grow >> 3, b = grow & 7;
            float v = g_totalH[(t*16 + k) * BB + b];
            unsigned hb = tf32_of(v);
            ah[kt][jj] = hb;
            al[kt][jj] = tf32_of(v - __uint_as_float(hb));
        }
    }

    float st0 = 0.f, st1 = 0.f;
    if (!PASS1) {
        st0 = g_rowstat[rowBase + g];
        st1 = g_rowstat[rowBase + g + 8];
    }

    float sum0 = 0.f, sum1 = 0.f;
    int vt0 = blockIdx.x * (VITER * 16);   // first v-tile index of this block

    const float* Bt = g_Wt + (size_t)vt0 * 128 + g * 8 + q * 2;  // per-thread base
    float* op0;
    float* op1;
    if (!PASS1) {
        size_t vc = (size_t)vt0 * 8 + q * 2;
        op0 = out + (size_t)(rowBase + g    ) * VV + vc;
        op1 = out + (size_t)(rowBase + g + 8) * VV + vc;
    }

    for (int it = 0; it < VITER; it++) {
        #pragma unroll
        for (int nt = 0; nt < 16; nt++) {
            // B fragments: one float2 per kt = {k=kt*8+q, k=kt*8+q+4} at n=g
            float2 Bk0 = __ldg((const float2*)Bt);
            float2 Bk1 = __ldg((const float2*)(Bt + 64));
            Bt += 128;
            unsigned b00 = __float_as_uint(Bk0.x), b01 = __float_as_uint(Bk0.y);
            unsigned b10 = __float_as_uint(Bk1.x), b11 = __float_as_uint(Bk1.y);

            float d0 = 0.f, d1 = 0.f, d2 = 0.f, d3 = 0.f;
            mma_tf32(d0,d1,d2,d3, ah[0][0],ah[0][1],ah[0][2],ah[0][3], b00,b01);
            mma_tf32(d0,d1,d2,d3, al[0][0],al[0][1],al[0][2],al[0][3], b00,b01);
            mma_tf32(d0,d1,d2,d3, ah[1][0],ah[1][1],ah[1][2],ah[1][3], b10,b11);
            mma_tf32(d0,d1,d2,d3, al[1][0],al[1][1],al[1][2],al[1][3], b10,b11);

            if (PASS1) {
                sum0 += __expf(d0) + __expf(d1);
                sum1 += __expf(d2) + __expf(d3);
            } else {
                *(float2*)op0 = make_float2(d0 - st0, d1 - st0);
                *(float2*)op1 = make_float2(d2 - st1, d3 - st1);
                op0 += 8; op1 += 8;
            }
        }
    }

    if (PASS1) {
        // reduce across the 4 q-lanes sharing each row-group g
        sum0 += __shfl_xor_sync(0xffffffffu, sum0, 1);
        sum0 += __shfl_xor_sync(0xffffffffu, sum0, 2);
        sum1 += __shfl_xor_sync(0xffffffffu, sum1, 1);
        sum1 += __shfl_xor_sync(0xffffffffu, sum1, 2);
        if (q == 0) {
            float* p = g_partial + (size_t)blockIdx.x * NROWS + rowBase;
            p[g    ] = sum0;
            p[g + 8] = sum1;
        }
    }
}

// ---------------- kernel: reduce partials -> log-sum-exp per row ----------------
__global__ void k_stat() {
    int r = blockIdx.x * blockDim.x + threadIdx.x;
    if (r >= NROWS) return;
    float s = 0.f;
    #pragma unroll
    for (int i = 0; i < VBLK; i++) s += g_partial[i * NROWS + r];
    g_rowstat[r] = logf(s);
}

// ---------------- launch ----------------
extern "C" void kernel_launch(void* const* d_in, const int* in_sizes, int n_in,
                              void* d_out, int out_size) {
    const int*   x   = (const int*)  d_in[0];
    const float* emb = (const float*)d_in[1];
    const float* Wx1 = (const float*)d_in[2];
    const float* bx1 = (const float*)d_in[3];
    const float* Wh1 = (const float*)d_in[4];
    const float* bh1 = (const float*)d_in[5];
    const float* Wx2 = (const float*)d_in[6];
    const float* bx2 = (const float*)d_in[7];
    const float* Wh2 = (const float*)d_in[8];
    const float* bh2 = (const float*)d_in[9];
    const float* Wo  = (const float*)d_in[10];
    float* out = (float*)d_out;

    dim3 gprep(125, 16);
    k_prep<<<gprep, 256>>>(Wo);
    k_embed<<<(NROWS + 255)/256, 256>>>(x, emb, Wx1, bx1, bh1, Wx2, bx2, bh2);
    k_rnn<<<4, 32>>>(Wh1, Wh2);
    dim3 grd(VBLK, NROWS/128), blk(256);
    k_pass<true ><<<grd, blk>>>(nullptr);
    k_stat<<<(NROWS + 255)/256, 256>>>();
    k_pass<false><<<grd, blk>>>(out);
}

// round 9
// speedup vs baseline: 1.5099x; 1.2954x over previous
#include <cuda_runtime.h>
#include <cstddef>

#define TT 1024
#define BB 8
#define VV 32000
#define EE 32
#define HH 8
#define NROWS (TT*BB)      // 8192
#define VBLK  25           // grid.x of pass kernels
#define VITER 10           // outer iters; per iter a warp covers 16 n8-tiles = 128 v

// ---------------- scratch (device globals; no allocation) ----------------
__device__ float  g_xp[2*TT*BB*HH];      // [dir][t][b][h]  input projections (+both biases)
__device__ float  g_totalH[TT*16*BB];    // [t][d][b]  d<8: forward h1, d>=8: backward h2
__device__ float  g_partial[VBLK*NROWS]; // per v-block partial sum-of-exp (deterministic)
__device__ float  g_rowstat[NROWS];      // log(sum exp) per row
__device__ float  g_Wt[16*VV];           // tiled tf32 output weights, 2 MB
// layout: tile vt (8 v): pos = vt*128 + n*16 + (k&3)*4 + (k>>2)
// thread (g=n, q) loads float4 {k=q, k=q+4, k=q+8, k=q+12} at vt*128 + g*16 + q*4

// tf32 round (rna)
__device__ __forceinline__ unsigned tf32_of(float x) {
    unsigned r;
    asm("cvt.rna.tf32.f32 %0, %1;" : "=r"(r) : "f"(x));
    return r;
}

// m16n8k8 tf32 mma, D += A*B (C aliased to D)
__device__ __forceinline__ void mma_tf32(float& d0, float& d1, float& d2, float& d3,
                                         unsigned a0, unsigned a1, unsigned a2, unsigned a3,
                                         unsigned b0, unsigned b1) {
    asm("mma.sync.aligned.m16n8k8.row.col.f32.tf32.tf32.f32 "
        "{%0,%1,%2,%3}, {%4,%5,%6,%7}, {%8,%9}, {%0,%1,%2,%3};"
        : "+f"(d0), "+f"(d1), "+f"(d2), "+f"(d3)
        : "r"(a0), "r"(a1), "r"(a2), "r"(a3), "r"(b0), "r"(b1));
}

// ---------------- kernel 0: W -> tiled single-tf32, float4-coalesced frags ----
__global__ void k_prep(const float* __restrict__ Wo) {
    int v = blockIdx.x * 256 + threadIdx.x;   // grid.x = 125
    int k = blockIdx.y;                        // 16
    float x = __ldg(Wo + (size_t)k * VV + v);
    int pos = (v >> 3) * 128 + (v & 7) * 16 + (k & 3) * 4 + (k >> 2);
    g_Wt[pos] = __uint_as_float(tf32_of(x));
}

// ---------------- kernel 1: embedding gather + x-projections ----------------
__global__ void k_embed(const int* __restrict__ x, const float* __restrict__ emb,
                        const float* __restrict__ Wx1, const float* __restrict__ bx1,
                        const float* __restrict__ bh1,
                        const float* __restrict__ Wx2, const float* __restrict__ bx2,
                        const float* __restrict__ bh2) {
    int tid = blockIdx.x * blockDim.x + threadIdx.x;   // (t,b) flat
    if (tid >= NROWS) return;
    int idx = x[tid];
    const float4* em = (const float4*)(emb + (size_t)idx * EE);
    float e[EE];
    #pragma unroll
    for (int q = 0; q < 8; q++) {
        float4 v = __ldg(em + q);
        e[4*q] = v.x; e[4*q+1] = v.y; e[4*q+2] = v.z; e[4*q+3] = v.w;
    }
    #pragma unroll
    for (int j = 0; j < HH; j++) {
        float s1 = bx1[j] + bh1[j];
        float s2 = bx2[j] + bh2[j];
        #pragma unroll
        for (int k = 0; k < EE; k++) {
            s1 = fmaf(e[k], __ldg(Wx1 + k*HH + j), s1);
            s2 = fmaf(e[k], __ldg(Wx2 + k*HH + j), s2);
        }
        g_xp[tid*HH + j] = s1;
        g_xp[TT*BB*HH + tid*HH + j] = s2;
    }
}

// ---------------- kernel 2: the two sequential RNNs ----------------
// 4 blocks x 32 threads. lane = chainLocal*8 + j; 4 chains per warp.
// h exchanged via shfl; xp loads prefetched 4 steps ahead.
// Emits h BEFORE the update (matches the reference scan).
__global__ void k_rnn(const float* __restrict__ Wh1, const float* __restrict__ Wh2) {
    int lane = threadIdx.x;
    int j = lane & 7;
    int c = blockIdx.x * 4 + (lane >> 3);   // chain id 0..15
    int dir = c >> 3, b = c & 7;
    int grp = lane & ~7;                    // base lane of this chain's group
    const float* Wh = dir ? Wh2 : Wh1;
    float w[HH];
    #pragma unroll
    for (int k = 0; k < HH; k++) w[k] = __ldg(Wh + k*HH + j);

    const float* xp = g_xp + dir * (TT*BB*HH);
    float h = 0.f;

    // depth-4 prefetch ring
    float pf[4];
    #pragma unroll
    for (int p = 0; p < 4; p++) {
        int t = dir ? (TT - 1 - p) : p;
        pf[p] = __ldg(xp + (t*BB + b) * HH + j);
    }

    #pragma unroll 4
    for (int s = 0; s < TT; s++) {
        int slot = s & 3;
        float xv = pf[slot];
        if (s + 4 < TT) {
            int t4 = dir ? (TT - 1 - (s + 4)) : (s + 4);
            pf[slot] = __ldg(xp + (t4*BB + b) * HH + j);
        }
        int t = dir ? (TT - 1 - s) : s;
        // emit pre-update hidden state
        g_totalH[(t*16 + dir*8 + j) * BB + b] = h;
        // z_j = xv + sum_k h_k * Wh[k][j]   (tree form)
        float h0 = __shfl_sync(0xffffffffu, h, grp + 0);
        float h1 = __shfl_sync(0xffffffffu, h, grp + 1);
        float h2 = __shfl_sync(0xffffffffu, h, grp + 2);
        float h3 = __shfl_sync(0xffffffffu, h, grp + 3);
        float h4 = __shfl_sync(0xffffffffu, h, grp + 4);
        float h5 = __shfl_sync(0xffffffffu, h, grp + 5);
        float h6 = __shfl_sync(0xffffffffu, h, grp + 6);
        float h7 = __shfl_sync(0xffffffffu, h, grp + 7);
        float t0 = fmaf(h1, w[1], h0 * w[0]);
        float t1 = fmaf(h3, w[3], h2 * w[2]);
        float t2 = fmaf(h5, w[5], h4 * w[4]);
        float t3 = fmaf(h7, w[7], h6 * w[6]);
        float z  = xv + ((t0 + t1) + (t2 + t3));
        h = __fdividef(1.f, 1.f + __expf(-z));
    }
}

// ---------------- pass kernels: tf32 mma GEMM + softmax stats / output ----------------
// Warp owns 16 rows, block 256 = 128 rows, grid (VBLK, 64).
// Plain tf32 x tf32: 2 MMAs + 1 LDG.128 per warp-tile (error ~7e-5 << 1e-3 gate).
template <bool PASS1>
__global__ __launch_bounds__(256) void k_pass(float* __restrict__ out) {
    int lane = threadIdx.x & 31, w = threadIdx.x >> 5;
    int g = lane >> 2, q = lane & 3;
    int rowBase = blockIdx.y * 128 + w * 16;

    // A fragments, loaded once. jj: row g+(jj&1)*8, col q+(jj>>1)*4
    unsigned ah[2][4];
    #pragma unroll
    for (int kt = 0; kt < 2; kt++) {
        #pragma unroll
        for (int jj = 0; jj < 4; jj++) {
            int r = g + (jj & 1) * 8;
            int k = kt * 8 + q + ((jj >> 1) ? 4 : 0);
            int grow = rowBase + r, t = grow >> 3, b = grow & 7;
            ah[kt][jj] = tf32_of(g_totalH[(t*16 + k) * BB + b]);
        }
    }

    float st0 = 0.f, st1 = 0.f;
    if (!PASS1) {
        st0 = g_rowstat[rowBase + g];
        st1 = g_rowstat[rowBase + g + 8];
    }

    float sum0 = 0.f, sum1 = 0.f;
    int vt0 = blockIdx.x * (VITER * 16);   // first v-tile index of this block

    const float4* Bt = (const float4*)(g_Wt + (size_t)vt0 * 128 + g * 16 + q * 4);
    float* op0;
    float* op1;
    if (!PASS1) {
        size_t vc = (size_t)vt0 * 8 + q * 2;
        op0 = out + (size_t)(rowBase + g    ) * VV + vc;
        op1 = out + (size_t)(rowBase + g + 8) * VV + vc;
    }

    for (int it = 0; it < VITER; it++) {
        #pragma unroll
        for (int nt = 0; nt < 16; nt++) {
            // B fragments: {k=q, q+4, q+8, q+12} at n=g in one LDG.128
            float4 B = __ldg(Bt);
            Bt += 32;                       // 128 floats = 32 float4 per tile
            unsigned b00 = __float_as_uint(B.x), b01 = __float_as_uint(B.y);
            unsigned b10 = __float_as_uint(B.z), b11 = __float_as_uint(B.w);

            float d0 = 0.f, d1 = 0.f, d2 = 0.f, d3 = 0.f;
            mma_tf32(d0,d1,d2,d3, ah[0][0],ah[0][1],ah[0][2],ah[0][3], b00,b01);
            mma_tf32(d0,d1,d2,d3, ah[1][0],ah[1][1],ah[1][2],ah[1][3], b10,b11);

            if (PASS1) {
                sum0 += __expf(d0) + __expf(d1);
                sum1 += __expf(d2) + __expf(d3);
            } else {
                *(float2*)op0 = make_float2(d0 - st0, d1 - st0);
                *(float2*)op1 = make_float2(d2 - st1, d3 - st1);
                op0 += 8; op1 += 8;
            }
        }
    }

    if (PASS1) {
        // reduce across the 4 q-lanes sharing each row-group g
        sum0 += __shfl_xor_sync(0xffffffffu, sum0, 1);
        sum0 += __shfl_xor_sync(0xffffffffu, sum0, 2);
        sum1 += __shfl_xor_sync(0xffffffffu, sum1, 1);
        sum1 += __shfl_xor_sync(0xffffffffu, sum1, 2);
        if (q == 0) {
            float* p = g_partial + (size_t)blockIdx.x * NROWS + rowBase;
            p[g    ] = sum0;
            p[g + 8] = sum1;
        }
    }
}

// ---------------- kernel: reduce partials -> log-sum-exp per row ----------------
__global__ void k_stat() {
    int r = blockIdx.x * blockDim.x + threadIdx.x;
    if (r >= NROWS) return;
    float s = 0.f;
    #pragma unroll
    for (int i = 0; i < VBLK; i++) s += g_partial[i * NROWS + r];
    g_rowstat[r] = logf(s);
}

// ---------------- launch ----------------
extern "C" void kernel_launch(void* const* d_in, const int* in_sizes, int n_in,
                              void* d_out, int out_size) {
    const int*   x   = (const int*)  d_in[0];
    const float* emb = (const float*)d_in[1];
    const float* Wx1 = (const float*)d_in[2];
    const float* bx1 = (const float*)d_in[3];
    const float* Wh1 = (const float*)d_in[4];
    const float* bh1 = (const float*)d_in[5];
    const float* Wx2 = (const float*)d_in[6];
    const float* bx2 = (const float*)d_in[7];
    const float* Wh2 = (const float*)d_in[8];
    const float* bh2 = (const float*)d_in[9];
    const float* Wo  = (const float*)d_in[10];
    float* out = (float*)d_out;

    dim3 gprep(125, 16);
    k_prep<<<gprep, 256>>>(Wo);
    k_embed<<<(NROWS + 255)/256, 256>>>(x, emb, Wx1, bx1, bh1, Wx2, bx2, bh2);
    k_rnn<<<4, 32>>>(Wh1, Wh2);
    dim3 grd(VBLK, NROWS/128), blk(256);
    k_pass<true ><<<grd, blk>>>(nullptr);
    k_stat<<<(NROWS + 255)/256, 256>>>();
    k_pass<false><<<grd, blk>>>(out);
}

// round 10
// speedup vs baseline: 1.5707x; 1.0403x over previous
#include <cuda_runtime.h>
#include <cstddef>

#define TT 1024
#define BB 8
#define VV 32000
#define EE 32
#define HH 8
#define NROWS (TT*BB)      // 8192
#define VBLK  25           // grid.x of pass kernels
#define VITER 10           // outer iters; per iter a warp covers 16 n8-tiles = 128 v
#define LOG2E 1.4426950408889634f

// ---------------- scratch (device globals; no allocation) ----------------
__device__ float  g_xp[2*TT*BB*HH];      // [dir][t][b][h]  -log2e * (input proj + biases)
__device__ float  g_totalH[TT*2*BB*HH];  // [t][dir][b][j]  coalesced for the rnn store
__device__ float  g_partial[VBLK*NROWS]; // per v-block partial sum-of-exp (deterministic)
__device__ float  g_rowstat[NROWS];      // log(sum exp) per row
__device__ float  g_Wt[16*VV];           // tiled tf32 W (natural scale, pass2), 2 MB
__device__ float  g_Wt1[16*VV];          // tiled tf32 W * log2e (pass1), 2 MB
// tile layout: vt (8 v): pos = vt*128 + n*16 + (k&3)*4 + (k>>2)
// thread (g=n, q) loads float4 {k=q, k=q+4, k=q+8, k=q+12} at vt*128 + g*16 + q*4

// tf32 round (rna)
__device__ __forceinline__ unsigned tf32_of(float x) {
    unsigned r;
    asm("cvt.rna.tf32.f32 %0, %1;" : "=r"(r) : "f"(x));
    return r;
}
__device__ __forceinline__ float ex2(float x) {
    float r; asm("ex2.approx.f32 %0, %1;" : "=f"(r) : "f"(x)); return r;
}
__device__ __forceinline__ float rcp(float x) {
    float r; asm("rcp.approx.f32 %0, %1;" : "=f"(r) : "f"(x)); return r;
}

// m16n8k8 tf32 mma, D += A*B (C aliased to D)
__device__ __forceinline__ void mma_tf32(float& d0, float& d1, float& d2, float& d3,
                                         unsigned a0, unsigned a1, unsigned a2, unsigned a3,
                                         unsigned b0, unsigned b1) {
    asm("mma.sync.aligned.m16n8k8.row.col.f32.tf32.tf32.f32 "
        "{%0,%1,%2,%3}, {%4,%5,%6,%7}, {%8,%9}, {%0,%1,%2,%3};"
        : "+f"(d0), "+f"(d1), "+f"(d2), "+f"(d3)
        : "r"(a0), "r"(a1), "r"(a2), "r"(a3), "r"(b0), "r"(b1));
}

// ---------------- kernel 0: W -> tiled tf32 (natural + log2e-scaled copies) ----
__global__ void k_prep(const float* __restrict__ Wo) {
    int v = blockIdx.x * 256 + threadIdx.x;   // grid.x = 125
    int k = blockIdx.y;                        // 16
    float x = __ldg(Wo + (size_t)k * VV + v);
    int pos = (v >> 3) * 128 + (v & 7) * 16 + (k & 3) * 4 + (k >> 2);
    g_Wt [pos] = __uint_as_float(tf32_of(x));
    g_Wt1[pos] = __uint_as_float(tf32_of(x * LOG2E));
}

// ---------------- kernel 1: embedding gather + x-projections ----------------
// stores xp' = -log2e * (e@Wx + bx + bh) so the rnn uses ex2 directly
__global__ void k_embed(const int* __restrict__ x, const float* __restrict__ emb,
                        const float* __restrict__ Wx1, const float* __restrict__ bx1,
                        const float* __restrict__ bh1,
                        const float* __restrict__ Wx2, const float* __restrict__ bx2,
                        const float* __restrict__ bh2) {
    int tid = blockIdx.x * blockDim.x + threadIdx.x;   // (t,b) flat
    if (tid >= NROWS) return;
    int idx = x[tid];
    const float4* em = (const float4*)(emb + (size_t)idx * EE);
    float e[EE];
    #pragma unroll
    for (int q = 0; q < 8; q++) {
        float4 v = __ldg(em + q);
        e[4*q] = v.x; e[4*q+1] = v.y; e[4*q+2] = v.z; e[4*q+3] = v.w;
    }
    #pragma unroll
    for (int j = 0; j < HH; j++) {
        float s1 = bx1[j] + bh1[j];
        float s2 = bx2[j] + bh2[j];
        #pragma unroll
        for (int k = 0; k < EE; k++) {
            s1 = fmaf(e[k], __ldg(Wx1 + k*HH + j), s1);
            s2 = fmaf(e[k], __ldg(Wx2 + k*HH + j), s2);
        }
        g_xp[tid*HH + j] = s1 * (-LOG2E);
        g_xp[TT*BB*HH + tid*HH + j] = s2 * (-LOG2E);
    }
}

// ---------------- kernel 2: the two sequential RNNs ----------------
// 4 blocks x 32 threads. lane = chainLocal*8 + j; 4 chains per warp.
// Weights pre-scaled by -log2e so sigmoid = rcp(1 + ex2(z')).
// totalH store is one contiguous 128B line per warp per step.
// Emits h BEFORE the update (matches the reference scan).
__global__ void k_rnn(const float* __restrict__ Wh1, const float* __restrict__ Wh2) {
    int lane = threadIdx.x;
    int j = lane & 7;
    int c = blockIdx.x * 4 + (lane >> 3);   // chain id 0..15
    int dir = c >> 3, b = c & 7;
    int grp = lane & ~7;                    // base lane of this chain's group
    const float* Wh = dir ? Wh2 : Wh1;
    float w[HH];
    #pragma unroll
    for (int k = 0; k < HH; k++) w[k] = __ldg(Wh + k*HH + j) * (-LOG2E);

    const float* xp = g_xp + dir * (TT*BB*HH);
    float h = 0.f;

    // depth-4 prefetch ring
    float pf[4];
    #pragma unroll
    for (int p = 0; p < 4; p++) {
        int t = dir ? (TT - 1 - p) : p;
        pf[p] = __ldg(xp + (t*BB + b) * HH + j);
    }

    #pragma unroll 4
    for (int s = 0; s < TT; s++) {
        int slot = s & 3;
        float xv = pf[slot];
        if (s + 4 < TT) {
            int t4 = dir ? (TT - 1 - (s + 4)) : (s + 4);
            pf[slot] = __ldg(xp + (t4*BB + b) * HH + j);
        }
        int t = dir ? (TT - 1 - s) : s;
        // emit pre-update hidden state: [t][dir][b][j] -> coalesced per warp
        g_totalH[t*128 + dir*64 + b*8 + j] = h;
        // z' = xv' + sum_k h_k * w'_kj   (already -log2e scaled)
        float h0 = __shfl_sync(0xffffffffu, h, grp + 0);
        float h1 = __shfl_sync(0xffffffffu, h, grp + 1);
        float h2 = __shfl_sync(0xffffffffu, h, grp + 2);
        float h3 = __shfl_sync(0xffffffffu, h, grp + 3);
        float h4 = __shfl_sync(0xffffffffu, h, grp + 4);
        float h5 = __shfl_sync(0xffffffffu, h, grp + 5);
        float h6 = __shfl_sync(0xffffffffu, h, grp + 6);
        float h7 = __shfl_sync(0xffffffffu, h, grp + 7);
        float t0 = fmaf(h1, w[1], h0 * w[0]);
        float t1 = fmaf(h3, w[3], h2 * w[2]);
        float t2 = fmaf(h5, w[5], h4 * w[4]);
        float t3 = fmaf(h7, w[7], h6 * w[6]);
        float z  = xv + ((t0 + t1) + (t2 + t3));
        h = rcp(1.f + ex2(z));              // sigmoid
    }
}

// ---------------- pass kernels: tf32 mma GEMM + softmax stats / output ----------------
// Warp owns 16 rows, block 256 = 128 rows, grid (VBLK, 64).
// Plain tf32 x tf32: 2 MMAs + 1 LDG.128 per warp-tile.
// PASS1 uses the log2e-scaled W copy so exp = bare EX2.
template <bool PASS1>
__global__ __launch_bounds__(256) void k_pass(float* __restrict__ out) {
    int lane = threadIdx.x & 31, w = threadIdx.x >> 5;
    int g = lane >> 2, q = lane & 3;
    int rowBase = blockIdx.y * 128 + w * 16;

    // A fragments, loaded once. jj: row g+(jj&1)*8, col q+(jj>>1)*4
    unsigned ah[2][4];
    #pragma unroll
    for (int kt = 0; kt < 2; kt++) {
        #pragma unroll
        for (int jj = 0; jj < 4; jj++) {
            int r = g + (jj & 1) * 8;
            int k = kt * 8 + q + ((jj >> 1) ? 4 : 0);
            int grow = rowBase + r, t = grow >> 3, b = grow & 7;
            ah[kt][jj] = tf32_of(g_totalH[t*128 + (k >> 3)*64 + b*8 + (k & 7)]);
        }
    }

    float st0 = 0.f, st1 = 0.f;
    if (!PASS1) {
        st0 = g_rowstat[rowBase + g];
        st1 = g_rowstat[rowBase + g + 8];
    }

    float sum0 = 0.f, sum1 = 0.f;
    int vt0 = blockIdx.x * (VITER * 16);   // first v-tile index of this block

    const float* Wsrc = PASS1 ? g_Wt1 : g_Wt;
    const float4* Bt = (const float4*)(Wsrc + (size_t)vt0 * 128 + g * 16 + q * 4);
    float* op0;
    float* op1;
    if (!PASS1) {
        size_t vc = (size_t)vt0 * 8 + q * 2;
        op0 = out + (size_t)(rowBase + g    ) * VV + vc;
        op1 = out + (size_t)(rowBase + g + 8) * VV + vc;
    }

    for (int it = 0; it < VITER; it++) {
        #pragma unroll
        for (int nt = 0; nt < 16; nt++) {
            // B fragments: {k=q, q+4, q+8, q+12} at n=g in one LDG.128
            float4 B = __ldg(Bt);
            Bt += 32;                       // 128 floats = 32 float4 per tile
            unsigned b00 = __float_as_uint(B.x), b01 = __float_as_uint(B.y);
            unsigned b10 = __float_as_uint(B.z), b11 = __float_as_uint(B.w);

            float d0 = 0.f, d1 = 0.f, d2 = 0.f, d3 = 0.f;
            mma_tf32(d0,d1,d2,d3, ah[0][0],ah[0][1],ah[0][2],ah[0][3], b00,b01);
            mma_tf32(d0,d1,d2,d3, ah[1][0],ah[1][1],ah[1][2],ah[1][3], b10,b11);

            if (PASS1) {
                // d is log2e-scaled: e^z = 2^d
                sum0 += ex2(d0) + ex2(d1);
                sum1 += ex2(d2) + ex2(d3);
            } else {
                *(float2*)op0 = make_float2(d0 - st0, d1 - st0);
                *(float2*)op1 = make_float2(d2 - st1, d3 - st1);
                op0 += 8; op1 += 8;
            }
        }
    }

    if (PASS1) {
        // reduce across the 4 q-lanes sharing each row-group g
        sum0 += __shfl_xor_sync(0xffffffffu, sum0, 1);
        sum0 += __shfl_xor_sync(0xffffffffu, sum0, 2);
        sum1 += __shfl_xor_sync(0xffffffffu, sum1, 1);
        sum1 += __shfl_xor_sync(0xffffffffu, sum1, 2);
        if (q == 0) {
            float* p = g_partial + (size_t)blockIdx.x * NROWS + rowBase;
            p[g    ] = sum0;
            p[g + 8] = sum1;
        }
    }
}

// ---------------- kernel: reduce partials -> log-sum-exp per row ----------------
__global__ void k_stat() {
    int r = blockIdx.x * blockDim.x + threadIdx.x;
    if (r >= NROWS) return;
    float s = 0.f;
    #pragma unroll
    for (int i = 0; i < VBLK; i++) s += g_partial[i * NROWS + r];
    g_rowstat[r] = logf(s);
}

// ---------------- launch ----------------
extern "C" void kernel_launch(void* const* d_in, const int* in_sizes, int n_in,
                              void* d_out, int out_size) {
    const int*   x   = (const int*)  d_in[0];
    const float* emb = (const float*)d_in[1];
    const float* Wx1 = (const float*)d_in[2];
    const float* bx1 = (const float*)d_in[3];
    const float* Wh1 = (const float*)d_in[4];
    const float* bh1 = (const float*)d_in[5];
    const float* Wx2 = (const float*)d_in[6];
    const float* bx2 = (const float*)d_in[7];
    const float* Wh2 = (const float*)d_in[8];
    const float* bh2 = (const float*)d_in[9];
    const float* Wo  = (const float*)d_in[10];
    float* out = (float*)d_out;

    dim3 gprep(125, 16);
    k_prep<<<gprep, 256>>>(Wo);
    k_embed<<<(NROWS + 255)/256, 256>>>(x, emb, Wx1, bx1, bh1, Wx2, bx2, bh2);
    k_rnn<<<4, 32>>>(Wh1, Wh2);
    dim3 grd(VBLK, NROWS/128), blk(256);
    k_pass<true ><<<grd, blk>>>(nullptr);
    k_stat<<<(NROWS + 255)/256, 256>>>();
    k_pass<false><<<grd, blk>>>(out);
}